// round 6
// baseline (speedup 1.0000x reference)
#include <cuda_runtime.h>

// LSTM: B=4096, T=512, IN=1, H=32, OUT=1
// Weights-in-registers warp kernel, f32x2-packed FMAs, MUFU.TANH activations.
// BALANCED LAUNCH: 296 CTAs = exactly 2 per SM. Flat warp id w: w<544 handles
// 4 elements, rest handle 3 (544*4+640*3=4096). Worst-case SM load drops from
// 32 to 28 elements (R5 had 108 SMs with 32 elems and 40 SMs with 16).

#define TT  512
#define HH  32
#define BB  4096
#define W4  544    // warps that carry 4 elements; the rest carry 3

typedef unsigned long long u64;

__device__ __forceinline__ u64 fma2(u64 a, u64 b, u64 c) {
    u64 d;
    asm("fma.rn.f32x2 %0, %1, %2, %3;" : "=l"(d) : "l"(a), "l"(b), "l"(c));
    return d;
}
__device__ __forceinline__ float unpack_sum(u64 v) {
    float lo, hi;
    asm("mov.b64 {%0, %1}, %2;" : "=f"(lo), "=f"(hi) : "l"(v));
    return lo + hi;
}
__device__ __forceinline__ u64 pack2(float lo, float hi) {
    u64 d;
    asm("mov.b64 %0, {%1, %2};" : "=l"(d) : "f"(lo), "f"(hi));
    return d;
}
__device__ __forceinline__ float tanh_hw(float x) {
    float r;
    asm("tanh.approx.f32 %0, %1;" : "=f"(r) : "f"(x));
    return r;
}

// Per-warp LSTM over EPW batch elements. Weights shared in registers.
template <int EPW>
__device__ __forceinline__ void lstm_body(
    const float* __restrict__ x,
    const float* __restrict__ W_ih, const float* __restrict__ W_hh,
    const float* __restrict__ b_ih, const float* __restrict__ b_hh,
    const float* __restrict__ fc_w, const float* __restrict__ fc_b,
    float* __restrict__ out,
    float (*x_w)[TT],            // [4][TT]  (this warp's x staging, EPW used)
    float (*h_w)[4][HH],         // [2][4][HH] (this warp's h double buffer)
    int b0, int lane)
{
    // Stage x sequences (coalesced LDG.128).
    #pragma unroll
    for (int e = 0; e < EPW; e++) {
        const float4* xb4 = reinterpret_cast<const float4*>(x + (size_t)(b0 + e) * TT);
        float4* xs4 = reinterpret_cast<float4*>(x_w[e]);
        #pragma unroll
        for (int i = 0; i < TT / 4 / 32; i++)
            xs4[lane + i * 32] = xb4[lane + i * 32];
    }

    // Per-lane weights; sigmoid gates (0,1,3) pre-scaled by 0.5.
    u64   w[4][16];
    float wih[4], bias[4];
    #pragma unroll
    for (int gt = 0; gt < 4; gt++) {
        const int   row   = gt * HH + lane;
        const float scale = (gt == 2) ? 1.0f : 0.5f;
        const float4* wr = reinterpret_cast<const float4*>(W_hh + row * HH);
        #pragma unroll
        for (int q = 0; q < 8; q++) {
            float4 v = wr[q];
            w[gt][2 * q]     = pack2(v.x * scale, v.y * scale);
            w[gt][2 * q + 1] = pack2(v.z * scale, v.w * scale);
        }
        wih[gt]  = W_ih[row] * scale;
        bias[gt] = (b_ih[row] + b_hh[row]) * scale;
    }

    float c[EPW], hj[EPW];
    #pragma unroll
    for (int e = 0; e < EPW; e++) {
        h_w[0][e][lane] = 0.0f;
        c[e] = 0.0f; hj[e] = 0.0f;
    }
    __syncwarp();

    int p = 0;
    for (int t = 0; t < TT; t++) {
        u64 acc[EPW][4];
        #pragma unroll
        for (int e = 0; e < EPW; e++) {
            const float xt = x_w[e][t];
            #pragma unroll
            for (int gt = 0; gt < 4; gt++)
                acc[e][gt] = pack2(fmaf(xt, wih[gt], bias[gt]), 0.0f);
        }

        #pragma unroll
        for (int q = 0; q < 8; q++) {
            #pragma unroll
            for (int e = 0; e < EPW; e++) {
                ulonglong2 hv = reinterpret_cast<const ulonglong2*>(h_w[p][e])[q];
                #pragma unroll
                for (int gt = 0; gt < 4; gt++) {
                    acc[e][gt] = fma2(hv.x, w[gt][2 * q],     acc[e][gt]);
                    acc[e][gt] = fma2(hv.y, w[gt][2 * q + 1], acc[e][gt]);
                }
            }
        }

        #pragma unroll
        for (int e = 0; e < EPW; e++) {
            const float gi = fmaf(0.5f, tanh_hw(unpack_sum(acc[e][0])), 0.5f);
            const float gf = fmaf(0.5f, tanh_hw(unpack_sum(acc[e][1])), 0.5f);
            const float gg = tanh_hw(unpack_sum(acc[e][2]));
            const float go = fmaf(0.5f, tanh_hw(unpack_sum(acc[e][3])), 0.5f);
            c[e]  = fmaf(gf, c[e], gi * gg);
            hj[e] = go * tanh_hw(c[e]);
            h_w[p ^ 1][e][lane] = hj[e];
        }

        p ^= 1;
        __syncwarp();
    }

    // out[b] = dot(h, fc_w) + fc_b
    const float fw = fc_w[lane];
    float v[EPW];
    #pragma unroll
    for (int e = 0; e < EPW; e++) v[e] = hj[e] * fw;
    #pragma unroll
    for (int off = 16; off > 0; off >>= 1) {
        #pragma unroll
        for (int e = 0; e < EPW; e++)
            v[e] += __shfl_xor_sync(0xffffffffu, v[e], off);
    }
    if (lane == 0) {
        #pragma unroll
        for (int e = 0; e < EPW; e++)
            out[b0 + e] = v[e] + fc_b[0];
    }
}

__global__ __launch_bounds__(128, 2)
void lstm_bal_kernel(const float* __restrict__ x,
                     const float* __restrict__ W_ih,
                     const float* __restrict__ W_hh,
                     const float* __restrict__ b_ih,
                     const float* __restrict__ b_hh,
                     const float* __restrict__ fc_w,
                     const float* __restrict__ fc_b,
                     float* __restrict__ out)
{
    __shared__ __align__(16) float x_sh[4][4][TT];       // [warp][elem<=4][T] = 32KB
    __shared__ __align__(16) float h_sh[4][2][4][HH];    // [warp][buf][elem][j]

    const int tid  = threadIdx.x;
    const int wid  = tid >> 5;
    const int lane = tid & 31;
    const int w    = blockIdx.x * 4 + wid;   // flat warp id, 0..1183

    if (w < W4) {
        lstm_body<4>(x, W_ih, W_hh, b_ih, b_hh, fc_w, fc_b, out,
                     x_sh[wid], h_sh[wid], 4 * w, lane);
    } else {
        lstm_body<3>(x, W_ih, W_hh, b_ih, b_hh, fc_w, fc_b, out,
                     x_sh[wid], h_sh[wid], 4 * W4 + 3 * (w - W4), lane);
    }
}

extern "C" void kernel_launch(void* const* d_in, const int* in_sizes, int n_in,
                              void* d_out, int out_size) {
    const float* x    = (const float*)d_in[0];
    const float* W_ih = (const float*)d_in[1];
    const float* W_hh = (const float*)d_in[2];
    const float* b_ih = (const float*)d_in[3];
    const float* b_hh = (const float*)d_in[4];
    const float* fc_w = (const float*)d_in[5];
    const float* fc_b = (const float*)d_in[6];
    float* out = (float*)d_out;

    // 296 CTAs = exactly 2 per SM (148 SMs), single balanced wave.
    lstm_bal_kernel<<<296, 128>>>(x, W_ih, W_hh, b_ih, b_hh, fc_w, fc_b, out);
}

// round 8
// speedup vs baseline: 2.2583x; 2.2583x over previous
#include <cuda_runtime.h>
#include <cstdint>

// LSTM B=4096,T=512,IN=1,H=32,OUT=1 — tf32 mma.sync (sm_80+ PTX, assembles on
// plain sm_100; tcgen05 rejected by harness target).
// 128 CTAs x 128 threads; CTA owns 32 elems. Per step each warp computes a
// 32x32 slice of G[128 gate-rows x 32 elems] via 32x m16n8k8 tf32 MMAs with
// REGISTER accumulators. A-rows are permuted so warp w holds ALL 4 gates for
// hidden units j in [8w,8w+8): the c/h update never leaves registers.
// h round-trips through smem in B-fragment-permuted layout (conflict-free
// LDS.64), double-buffered -> exactly one bar.sync per step.

#define TT  512
#define HH  32
#define BB  4096
#define NB  32
#define XCH 64

typedef unsigned long long u64;

__device__ __forceinline__ uint32_t f2tf32(float f) {
    uint32_t r;
    asm("cvt.rna.tf32.f32 %0, %1;" : "=r"(r) : "f"(f));
    return r;
}
__device__ __forceinline__ float tanh_hw(float x) {
    float r;
    asm("tanh.approx.f32 %0, %1;" : "=f"(r) : "f"(x));
    return r;
}
__device__ __forceinline__ void mma_tf32(float* d, const uint32_t* a,
                                         const uint32_t* b) {
    asm volatile(
        "mma.sync.aligned.m16n8k8.row.col.f32.tf32.tf32.f32 "
        "{%0,%1,%2,%3}, {%4,%5,%6,%7}, {%8,%9}, {%0,%1,%2,%3};"
        : "+f"(d[0]), "+f"(d[1]), "+f"(d[2]), "+f"(d[3])
        : "r"(a[0]), "r"(a[1]), "r"(a[2]), "r"(a[3]), "r"(b[0]), "r"(b[1]));
}

// hperm layout (per buffer, 1024 u32 words):
//   word(n,k) = (n>>3)*256 + (k>>3)*64 + ((n&7)*4 + (k&3))*2 + ((k>>2)&1)
// so B-fragment load for (nt,kt) is LDS.64 at word = nt*256 + kt*64 + lane*2:
//   b0 = h[n=8nt+lane/4][k=8kt+lane%4], b1 = same with k+4.   (m16n8k8 .col B)

__global__ __launch_bounds__(128)
void lstm_mma_kernel(const float* __restrict__ x,      // [B,T]
                     const float* __restrict__ W_ih,   // [4H]
                     const float* __restrict__ W_hh,   // [4H,H]
                     const float* __restrict__ b_ih,   // [4H]
                     const float* __restrict__ b_hh,   // [4H]
                     const float* __restrict__ fc_w,   // [H]
                     const float* __restrict__ fc_b,   // [1]
                     float* __restrict__ out)          // [B]
{
    __shared__ __align__(16) uint32_t hbuf[2][1024];   // tf32 bits, permuted
    __shared__ __align__(16) float    xs[XCH * NB];    // x chunk [t][n]

    const int tid = threadIdx.x;
    const int w   = tid >> 5;          // warp = hidden block [8w,8w+8)
    const int l   = tid & 31;
    const int gid = l >> 2;            // 0..7
    const int lq  = l & 3;             // 0..3
    const int b0  = blockIdx.x * NB;
    const int j   = 8 * w + gid;       // hidden unit owned in epilogue

    // --- A fragments (persistent): warp-tile row m -> gate g=m>>3, hidden j.
    // a0/a2: rows gid (gate 2mt); a1/a3: rows gid+8 (gate 2mt+1). k = lq+8kt (+4).
    uint32_t af[2][4][4];
    #pragma unroll
    for (int mt = 0; mt < 2; mt++) {
        const int g0 = 2 * mt, g1 = 2 * mt + 1;
        const float s0 = (g0 == 2) ? 1.0f : 0.5f;
        const float s1 = (g1 == 2) ? 1.0f : 0.5f;
        const float* r0 = W_hh + (g0 * HH + j) * HH;
        const float* r1 = W_hh + (g1 * HH + j) * HH;
        #pragma unroll
        for (int kt = 0; kt < 4; kt++) {
            const int k0 = lq + 8 * kt;
            af[mt][kt][0] = f2tf32(r0[k0] * s0);
            af[mt][kt][1] = f2tf32(r1[k0] * s1);
            af[mt][kt][2] = f2tf32(r0[k0 + 4] * s0);
            af[mt][kt][3] = f2tf32(r1[k0 + 4] * s1);
        }
    }

    // --- per-gate wih/bias for hidden j (sigmoid gates pre-scaled x0.5)
    float wih[4], bias[4];
    #pragma unroll
    for (int g = 0; g < 4; g++) {
        const float sc = (g == 2) ? 1.0f : 0.5f;
        wih[g]  = W_ih[g * HH + j] * sc;
        bias[g] = (b_ih[g * HH + j] + b_hh[g * HH + j]) * sc;
    }

    // h_0 = 0
    for (int i = tid; i < 1024; i += 128) hbuf[0][i] = 0u;

    float c[8], hlast[8];
    #pragma unroll
    for (int q = 0; q < 8; q++) { c[q] = 0.0f; hlast[q] = 0.0f; }

    int p = 0;
    for (int t = 0; t < TT; t++) {
        if ((t & (XCH - 1)) == 0) {
            // refill x chunk [t, t+64): thread (n=tid>>2, part=tid&3)
            const int n = tid >> 2, part = tid & 3;
            const float4* src =
                reinterpret_cast<const float4*>(x + (size_t)(b0 + n) * TT + t + part * 16);
            #pragma unroll
            for (int i = 0; i < 4; i++) {
                float4 v = src[i];
                const int tt = part * 16 + i * 4;
                xs[(tt + 0) * NB + n] = v.x;
                xs[(tt + 1) * NB + n] = v.y;
                xs[(tt + 2) * NB + n] = v.z;
                xs[(tt + 3) * NB + n] = v.w;
            }
            __syncthreads();
        }

        // accumulator init: fold x*W_ih + bias (cols n = 2lq + dc + 8nt)
        float acc[2][4][4];
        #pragma unroll
        for (int nt = 0; nt < 4; nt++) {
            const float2 xv =
                *reinterpret_cast<const float2*>(&xs[(t & (XCH - 1)) * NB + 8 * nt + 2 * lq]);
            #pragma unroll
            for (int mt = 0; mt < 2; mt++) {
                acc[mt][nt][0] = fmaf(xv.x, wih[2 * mt],     bias[2 * mt]);
                acc[mt][nt][1] = fmaf(xv.y, wih[2 * mt],     bias[2 * mt]);
                acc[mt][nt][2] = fmaf(xv.x, wih[2 * mt + 1], bias[2 * mt + 1]);
                acc[mt][nt][3] = fmaf(xv.y, wih[2 * mt + 1], bias[2 * mt + 1]);
            }
        }

        // B fragments: conflict-free LDS.64 from permuted h
        uint32_t bf[4][4][2];
        #pragma unroll
        for (int nt = 0; nt < 4; nt++)
            #pragma unroll
            for (int kt = 0; kt < 4; kt++) {
                const u64 v = *reinterpret_cast<const u64*>(
                    &hbuf[p][nt * 256 + kt * 64 + l * 2]);
                bf[nt][kt][0] = (uint32_t)v;
                bf[nt][kt][1] = (uint32_t)(v >> 32);
            }

        // 32 MMAs: 8 independent accumulator chains of length 4
        #pragma unroll
        for (int nt = 0; nt < 4; nt++)
            #pragma unroll
            for (int mt = 0; mt < 2; mt++)
                #pragma unroll
                for (int kt = 0; kt < 4; kt++)
                    mma_tf32(acc[mt][nt], af[mt][kt], bf[nt][kt]);

        // epilogue: 8 cells (n = 2lq+dc+8nt, hidden j) entirely in registers
        #pragma unroll
        for (int nt = 0; nt < 4; nt++) {
            #pragma unroll
            for (int dc = 0; dc < 2; dc++) {
                const int q = nt * 2 + dc;
                const float gi = fmaf(0.5f, tanh_hw(acc[0][nt][dc]),     0.5f);
                const float gf = fmaf(0.5f, tanh_hw(acc[0][nt][2 + dc]), 0.5f);
                const float gg =             tanh_hw(acc[1][nt][dc]);
                const float go = fmaf(0.5f, tanh_hw(acc[1][nt][2 + dc]), 0.5f);
                c[q] = fmaf(gf, c[q], gi * gg);
                const float h = go * tanh_hw(c[q]);
                hlast[q] = h;
                // store to permuted layout: n&7 = 2lq+dc, k = j
                const int word = nt * 256 + w * 64 +
                                 ((2 * lq + dc) * 4 + (gid & 3)) * 2 + ((l >> 4) & 1);
                hbuf[p ^ 1][word] = f2tf32(h);
            }
        }

        __syncthreads();   // the only per-step barrier
        p ^= 1;
    }

    // out[n] = dot(h_T[n,:], fc_w) + fc_b  (read final h from hbuf[p])
    if (tid < NB) {
        const int n = tid;
        float s = fc_b[0];
        #pragma unroll
        for (int k = 0; k < HH; k++) {
            const int word = (n >> 3) * 256 + (k >> 3) * 64 +
                             ((n & 7) * 4 + (k & 3)) * 2 + ((k >> 2) & 1);
            s = fmaf(__uint_as_float(hbuf[p][word]), fc_w[k], s);
        }
        out[b0 + n] = s;
    }
}

extern "C" void kernel_launch(void* const* d_in, const int* in_sizes, int n_in,
                              void* d_out, int out_size) {
    const float* x    = (const float*)d_in[0];
    const float* W_ih = (const float*)d_in[1];
    const float* W_hh = (const float*)d_in[2];
    const float* b_ih = (const float*)d_in[3];
    const float* b_hh = (const float*)d_in[4];
    const float* fc_w = (const float*)d_in[5];
    const float* fc_b = (const float*)d_in[6];
    float* out = (float*)d_out;

    lstm_mma_kernel<<<BB / NB, 128>>>(x, W_ih, W_hh, b_ih, b_hh, fc_w, fc_b, out);
}

// round 9
// speedup vs baseline: 2.7411x; 1.2138x over previous
#include <cuda_runtime.h>
#include <cstdint>

// LSTM B=4096,T=512,IN=1,H=32,OUT=1 — tf32 mma.sync, register accumulators.
// R9: NB=8 elems/CTA, 512 CTAs (~3.5/SM, single wave) -> 3-4 independent
// warps per SMSP so per-step dependency chains interleave (R8 had 1 warp/SMSP,
// issue=31%). Warp w owns hidden units [8w,8w+8) of ALL 4 gates; c/h update
// never leaves registers. h round-trips via permuted smem (conflict-free
// LDS.64), double-buffered -> one bar.sync per step.

#define TT  512
#define HH  32
#define BB  4096
#define NB  8
#define XCH 64

typedef unsigned long long u64;

__device__ __forceinline__ uint32_t f2tf32(float f) {
    uint32_t r;
    asm("cvt.rna.tf32.f32 %0, %1;" : "=r"(r) : "f"(f));
    return r;
}
__device__ __forceinline__ float tanh_hw(float x) {
    float r;
    asm("tanh.approx.f32 %0, %1;" : "=f"(r) : "f"(x));
    return r;
}
__device__ __forceinline__ void mma_tf32(float* d, const uint32_t* a,
                                         const uint32_t* b) {
    asm volatile(
        "mma.sync.aligned.m16n8k8.row.col.f32.tf32.tf32.f32 "
        "{%0,%1,%2,%3}, {%4,%5,%6,%7}, {%8,%9}, {%0,%1,%2,%3};"
        : "+f"(d[0]), "+f"(d[1]), "+f"(d[2]), "+f"(d[3])
        : "r"(a[0]), "r"(a[1]), "r"(a[2]), "r"(a[3]), "r"(b[0]), "r"(b[1]));
}

// hbuf word(n,k) = (k>>3)*64 + ((n&7)*4 + (k&3))*2 + ((k>>2)&1)   (n<8)
// -> B-fragment (kt) = LDS.64 at word kt*64 + l*2:
//    b0 = h[n=l/4][k=8kt+l%4], b1 = same k+4  (m16n8k8 .col B layout)

__global__ __launch_bounds__(128, 4)
void lstm_mma8_kernel(const float* __restrict__ x,      // [B,T]
                      const float* __restrict__ W_ih,   // [4H]
                      const float* __restrict__ W_hh,   // [4H,H]
                      const float* __restrict__ b_ih,   // [4H]
                      const float* __restrict__ b_hh,   // [4H]
                      const float* __restrict__ fc_w,   // [H]
                      const float* __restrict__ fc_b,   // [1]
                      float* __restrict__ out)          // [B]
{
    __shared__ __align__(16) uint32_t hbuf[2][256];    // tf32 bits, permuted
    __shared__ __align__(16) float    xs[XCH * NB];    // x chunk [t][n]

    const int tid = threadIdx.x;
    const int w   = tid >> 5;
    const int l   = tid & 31;
    const int gid = l >> 2;            // 0..7
    const int lq  = l & 3;             // 0..3
    const int b0  = blockIdx.x * NB;
    const int j   = 8 * w + gid;       // hidden unit owned in epilogue

    // A fragments (persistent across all 512 steps); sigmoid rows x0.5.
    uint32_t af[2][4][4];
    #pragma unroll
    for (int mt = 0; mt < 2; mt++) {
        const int g0 = 2 * mt, g1 = 2 * mt + 1;
        const float s0 = (g0 == 2) ? 1.0f : 0.5f;
        const float s1 = (g1 == 2) ? 1.0f : 0.5f;
        const float* r0 = W_hh + (g0 * HH + j) * HH;
        const float* r1 = W_hh + (g1 * HH + j) * HH;
        #pragma unroll
        for (int kt = 0; kt < 4; kt++) {
            const int k0 = lq + 8 * kt;
            af[mt][kt][0] = f2tf32(r0[k0] * s0);
            af[mt][kt][1] = f2tf32(r1[k0] * s1);
            af[mt][kt][2] = f2tf32(r0[k0 + 4] * s0);
            af[mt][kt][3] = f2tf32(r1[k0 + 4] * s1);
        }
    }

    float wih[4], bias[4];
    #pragma unroll
    for (int g = 0; g < 4; g++) {
        const float sc = (g == 2) ? 1.0f : 0.5f;
        wih[g]  = W_ih[g * HH + j] * sc;
        bias[g] = (b_ih[g * HH + j] + b_hh[g * HH + j]) * sc;
    }

    for (int i = tid; i < 256; i += 128) hbuf[0][i] = 0u;

    float c[2] = {0.0f, 0.0f};

    int p = 0;
    for (int t = 0; t < TT; t++) {
        if ((t & (XCH - 1)) == 0) {
            // refill x chunk [t, t+64): thread (n = tid>>4, part = tid&15)
            const int n = tid >> 4, part = tid & 15;
            const float4 v = *reinterpret_cast<const float4*>(
                x + (size_t)(b0 + n) * TT + t + part * 4);
            xs[(part * 4 + 0) * NB + n] = v.x;
            xs[(part * 4 + 1) * NB + n] = v.y;
            xs[(part * 4 + 2) * NB + n] = v.z;
            xs[(part * 4 + 3) * NB + n] = v.w;
            __syncthreads();
        }

        // acc init: fold x*W_ih + bias (cols n = 2lq, 2lq+1)
        const float2 xv =
            *reinterpret_cast<const float2*>(&xs[(t & (XCH - 1)) * NB + 2 * lq]);
        float acc[2][4];
        #pragma unroll
        for (int mt = 0; mt < 2; mt++) {
            acc[mt][0] = fmaf(xv.x, wih[2 * mt],     bias[2 * mt]);
            acc[mt][1] = fmaf(xv.y, wih[2 * mt],     bias[2 * mt]);
            acc[mt][2] = fmaf(xv.x, wih[2 * mt + 1], bias[2 * mt + 1]);
            acc[mt][3] = fmaf(xv.y, wih[2 * mt + 1], bias[2 * mt + 1]);
        }

        // B fragments (conflict-free LDS.64)
        uint32_t bf[4][2];
        #pragma unroll
        for (int kt = 0; kt < 4; kt++) {
            const u64 v = *reinterpret_cast<const u64*>(&hbuf[p][kt * 64 + l * 2]);
            bf[kt][0] = (uint32_t)v;
            bf[kt][1] = (uint32_t)(v >> 32);
        }

        // 8 MMAs: 2 independent chains of 4
        #pragma unroll
        for (int mt = 0; mt < 2; mt++)
            #pragma unroll
            for (int kt = 0; kt < 4; kt++)
                mma_tf32(acc[mt], af[mt][kt], bf[kt]);

        // epilogue: 2 cells (n = 2lq+dc, hidden j), registers only
        #pragma unroll
        for (int dc = 0; dc < 2; dc++) {
            const float gi = fmaf(0.5f, tanh_hw(acc[0][dc]),     0.5f);
            const float gf = fmaf(0.5f, tanh_hw(acc[0][2 + dc]), 0.5f);
            const float gg =             tanh_hw(acc[1][dc]);
            const float go = fmaf(0.5f, tanh_hw(acc[1][2 + dc]), 0.5f);
            c[dc] = fmaf(gf, c[dc], gi * gg);
            const float h = go * tanh_hw(c[dc]);
            const int word = w * 64 + ((2 * lq + dc) * 4 + (gid & 3)) * 2 +
                             ((l >> 4) & 1);
            hbuf[p ^ 1][word] = f2tf32(h);
        }

        __syncthreads();
        p ^= 1;
    }

    // out[n] = dot(h[n,:], fc_w) + fc_b
    if (tid < NB) {
        const int n = tid;
        float s = fc_b[0];
        #pragma unroll
        for (int k = 0; k < HH; k++) {
            const int word = (k >> 3) * 64 + (n * 4 + (k & 3)) * 2 + ((k >> 2) & 1);
            s = fmaf(__uint_as_float(hbuf[p][word]), fc_w[k], s);
        }
        out[b0 + n] = s;
    }
}

extern "C" void kernel_launch(void* const* d_in, const int* in_sizes, int n_in,
                              void* d_out, int out_size) {
    const float* x    = (const float*)d_in[0];
    const float* W_ih = (const float*)d_in[1];
    const float* W_hh = (const float*)d_in[2];
    const float* b_ih = (const float*)d_in[3];
    const float* b_hh = (const float*)d_in[4];
    const float* fc_w = (const float*)d_in[5];
    const float* fc_b = (const float*)d_in[6];
    float* out = (float*)d_out;

    lstm_mma8_kernel<<<BB / NB, 128>>>(x, W_ih, W_hh, b_ih, b_hh, fc_w, fc_b, out);
}

// round 10
// speedup vs baseline: 2.9608x; 1.0802x over previous
#include <cuda_runtime.h>
#include <cstdint>

// LSTM B=4096,T=512,IN=1,H=32,OUT=1 — tf32 mma.sync, register accumulators.
// R10: R9 (512 CTAs, NB=8, one bar.sync/step) with the per-step critical
// chain shortened: MMA chains split 4-deep -> 2x2-deep + FADD merge, t-loop
// unrolled x2 (static buffer parity, hoisted addresses), h stored as raw
// fp32 bits (tf32 datapath truncates; saves 2 cvt/step/thread).

#define TT  512
#define HH  32
#define BB  4096
#define NB  8
#define XCH 64

typedef unsigned long long u64;

__device__ __forceinline__ uint32_t f2tf32(float f) {
    uint32_t r;
    asm("cvt.rna.tf32.f32 %0, %1;" : "=r"(r) : "f"(f));
    return r;
}
__device__ __forceinline__ float tanh_hw(float x) {
    float r;
    asm("tanh.approx.f32 %0, %1;" : "=f"(r) : "f"(x));
    return r;
}
__device__ __forceinline__ void mma_tf32(float* d, const uint32_t* a,
                                         const uint32_t* b) {
    asm volatile(
        "mma.sync.aligned.m16n8k8.row.col.f32.tf32.tf32.f32 "
        "{%0,%1,%2,%3}, {%4,%5,%6,%7}, {%8,%9}, {%0,%1,%2,%3};"
        : "+f"(d[0]), "+f"(d[1]), "+f"(d[2]), "+f"(d[3])
        : "r"(a[0]), "r"(a[1]), "r"(a[2]), "r"(a[3]), "r"(b[0]), "r"(b[1]));
}

__global__ __launch_bounds__(128, 4)
void lstm_mma10_kernel(const float* __restrict__ x,      // [B,T]
                       const float* __restrict__ W_ih,   // [4H]
                       const float* __restrict__ W_hh,   // [4H,H]
                       const float* __restrict__ b_ih,   // [4H]
                       const float* __restrict__ b_hh,   // [4H]
                       const float* __restrict__ fc_w,   // [H]
                       const float* __restrict__ fc_b,   // [1]
                       float* __restrict__ out)          // [B]
{
    __shared__ __align__(16) uint32_t hbuf[2][256];    // h bits (fp32), permuted
    __shared__ __align__(16) float    xs[XCH * NB];    // x chunk [t][n]

    const int tid = threadIdx.x;
    const int w   = tid >> 5;
    const int l   = tid & 31;
    const int gid = l >> 2;            // 0..7
    const int lq  = l & 3;             // 0..3
    const int b0  = blockIdx.x * NB;
    const int j   = 8 * w + gid;       // hidden unit owned in epilogue

    // A fragments (persistent); sigmoid rows pre-scaled x0.5.
    uint32_t af[2][4][4];
    #pragma unroll
    for (int mt = 0; mt < 2; mt++) {
        const int g0 = 2 * mt, g1 = 2 * mt + 1;
        const float s0 = (g0 == 2) ? 1.0f : 0.5f;
        const float s1 = (g1 == 2) ? 1.0f : 0.5f;
        const float* r0 = W_hh + (g0 * HH + j) * HH;
        const float* r1 = W_hh + (g1 * HH + j) * HH;
        #pragma unroll
        for (int kt = 0; kt < 4; kt++) {
            const int k0 = lq + 8 * kt;
            af[mt][kt][0] = f2tf32(r0[k0] * s0);
            af[mt][kt][1] = f2tf32(r1[k0] * s1);
            af[mt][kt][2] = f2tf32(r0[k0 + 4] * s0);
            af[mt][kt][3] = f2tf32(r1[k0 + 4] * s1);
        }
    }

    float wih[4], bias[4];
    #pragma unroll
    for (int g = 0; g < 4; g++) {
        const float sc = (g == 2) ? 1.0f : 0.5f;
        wih[g]  = W_ih[g * HH + j] * sc;
        bias[g] = (b_ih[g * HH + j] + b_hh[g * HH + j]) * sc;
    }

    for (int i = tid; i < 256; i += 128) hbuf[0][i] = 0u;

    // Hoisted addresses (words): B-fragment base per buffer; STS word per buffer.
    const uint32_t* bfp[2] = { &hbuf[0][l * 2], &hbuf[1][l * 2] };
    const int stw = w * 64 + ((2 * lq) * 4 + (gid & 3)) * 2 + ((l >> 4) & 1);
    uint32_t* stp[2] = { &hbuf[0][stw], &hbuf[1][stw] };
    // store word for dc=1 is stw + 8 (n&7 -> +1 => +4*2 words)

    float c[2] = {0.0f, 0.0f};

    #pragma unroll 1
    for (int tb = 0; tb < TT; tb += 2) {
        if ((tb & (XCH - 1)) == 0) {
            const int n = tid >> 4, part = tid & 15;
            const float4 v = *reinterpret_cast<const float4*>(
                x + (size_t)(b0 + n) * TT + tb + part * 4);
            xs[(part * 4 + 0) * NB + n] = v.x;
            xs[(part * 4 + 1) * NB + n] = v.y;
            xs[(part * 4 + 2) * NB + n] = v.z;
            xs[(part * 4 + 3) * NB + n] = v.w;
            __syncthreads();
        }

        #pragma unroll
        for (int ph = 0; ph < 2; ph++) {            // step t = tb + ph, buffer = ph^... p starts 0
            const int t = tb + ph;
            const int p = ph & 1;                    // tb even => parity == ph

            // acc init (xs only — independent of the h exchange)
            const float2 xv = *reinterpret_cast<const float2*>(
                &xs[(t & (XCH - 1)) * NB + 2 * lq]);
            float accA[2][4], accB[2][4];
            #pragma unroll
            for (int mt = 0; mt < 2; mt++) {
                accA[mt][0] = fmaf(xv.x, wih[2 * mt],     bias[2 * mt]);
                accA[mt][1] = fmaf(xv.y, wih[2 * mt],     bias[2 * mt]);
                accA[mt][2] = fmaf(xv.x, wih[2 * mt + 1], bias[2 * mt + 1]);
                accA[mt][3] = fmaf(xv.y, wih[2 * mt + 1], bias[2 * mt + 1]);
                accB[mt][0] = 0.f; accB[mt][1] = 0.f;
                accB[mt][2] = 0.f; accB[mt][3] = 0.f;
            }

            // B fragments (conflict-free LDS.64)
            uint32_t bf[4][2];
            #pragma unroll
            for (int kt = 0; kt < 4; kt++) {
                const u64 v = *reinterpret_cast<const u64*>(bfp[p] + kt * 64);
                bf[kt][0] = (uint32_t)v;
                bf[kt][1] = (uint32_t)(v >> 32);
            }

            // 2 gates-pairs x (2 chains of depth 2)
            #pragma unroll
            for (int mt = 0; mt < 2; mt++) {
                mma_tf32(accA[mt], af[mt][0], bf[0]);
                mma_tf32(accB[mt], af[mt][2], bf[2]);
                mma_tf32(accA[mt], af[mt][1], bf[1]);
                mma_tf32(accB[mt], af[mt][3], bf[3]);
            }
            float acc[2][4];
            #pragma unroll
            for (int mt = 0; mt < 2; mt++)
                #pragma unroll
                for (int q = 0; q < 4; q++)
                    acc[mt][q] = accA[mt][q] + accB[mt][q];

            // epilogue: 2 cells, registers only; h stored as raw fp32 bits
            #pragma unroll
            for (int dc = 0; dc < 2; dc++) {
                const float gi = fmaf(0.5f, tanh_hw(acc[0][dc]),     0.5f);
                const float gf = fmaf(0.5f, tanh_hw(acc[0][2 + dc]), 0.5f);
                const float gg =             tanh_hw(acc[1][dc]);
                const float go = fmaf(0.5f, tanh_hw(acc[1][2 + dc]), 0.5f);
                c[dc] = fmaf(gf, c[dc], gi * gg);
                const float h = go * tanh_hw(c[dc]);
                stp[p ^ 1][dc * 8] = __float_as_uint(h);
            }

            __syncthreads();
        }
    }

    // out[n] = dot(h[n,:], fc_w) + fc_b   (final h is in hbuf[0]: T even)
    if (tid < NB) {
        const int n = tid;
        float s = fc_b[0];
        #pragma unroll
        for (int k = 0; k < HH; k++) {
            const int word = (k >> 3) * 64 + (n * 4 + (k & 3)) * 2 + ((k >> 2) & 1);
            s = fmaf(__uint_as_float(hbuf[0][word]), fc_w[k], s);
        }
        out[b0 + n] = s;
    }
}

extern "C" void kernel_launch(void* const* d_in, const int* in_sizes, int n_in,
                              void* d_out, int out_size) {
    const float* x    = (const float*)d_in[0];
    const float* W_ih = (const float*)d_in[1];
    const float* W_hh = (const float*)d_in[2];
    const float* b_ih = (const float*)d_in[3];
    const float* b_hh = (const float*)d_in[4];
    const float* fc_w = (const float*)d_in[5];
    const float* fc_b = (const float*)d_in[6];
    float* out = (float*)d_out;

    lstm_mma10_kernel<<<BB / NB, 128>>>(x, W_ih, W_hh, b_ih, b_hh, fc_w, fc_b, out);
}

// round 11
// speedup vs baseline: 3.2670x; 1.1034x over previous
#include <cuda_runtime.h>
#include <cuda_bf16.h>
#include <cstdint>

// LSTM B=4096,T=512,IN=1,H=32,OUT=1 — bf16 m16n8k16 mma.sync, fp32 accum,
// fp32 cell state in registers.
// 512 CTAs x 128 thr (NB=8 elems/CTA, ~3.5 CTAs/SM single wave). Warp w owns
// hidden units [8w,8w+8) of ALL 4 gates; per step: 4 HMMAs (2 chains of 2),
// epilogue entirely in registers, h re-packed to bf16x2 smem (one LDS.64 per
// B fragment), double-buffered -> one bar.sync per step.

#define TT  512
#define HH  32
#define BB  4096
#define NB  8
#define XCH 64

typedef unsigned long long u64;

__device__ __forceinline__ uint32_t pack_bf16(float lo, float hi) {
    uint32_t r;                        // first src -> upper half
    asm("cvt.rn.bf16x2.f32 %0, %1, %2;" : "=r"(r) : "f"(hi), "f"(lo));
    return r;
}
__device__ __forceinline__ float tanh_hw(float x) {
    float r;
    asm("tanh.approx.f32 %0, %1;" : "=f"(r) : "f"(x));
    return r;
}
__device__ __forceinline__ void mma_bf16(float* d, const uint32_t* a,
                                         const uint32_t* b) {
    asm volatile(
        "mma.sync.aligned.m16n8k16.row.col.f32.bf16.bf16.f32 "
        "{%0,%1,%2,%3}, {%4,%5,%6,%7}, {%8,%9}, {%0,%1,%2,%3};"
        : "+f"(d[0]), "+f"(d[1]), "+f"(d[2]), "+f"(d[3])
        : "r"(a[0]), "r"(a[1]), "r"(a[2]), "r"(a[3]), "r"(b[0]), "r"(b[1]));
}

// hbuf: 128 u32 words/buffer of bf16x2. kp = k/2 in 0..15 decomposes as
// kt=kp>>3, r=(kp>>2)&1, lqk=kp&3; word(n,kp) = kt*64 + lqk*16 + n*2 + r.
// B-fragment (kt) for lane l (n=l>>2, lq=l&3): LDS.64 at word kt*64+lq*16+(l>>2)*2
//   -> lo reg = {h[2lq? ...]} exactly b0={B[k=2lq][n],B[2lq+1][n]}, hi reg = k+8,+9.

__global__ __launch_bounds__(128, 4)
void lstm_bf16_kernel(const float* __restrict__ x,      // [B,T]
                      const float* __restrict__ W_ih,   // [4H]
                      const float* __restrict__ W_hh,   // [4H,H]
                      const float* __restrict__ b_ih,   // [4H]
                      const float* __restrict__ b_hh,   // [4H]
                      const float* __restrict__ fc_w,   // [H]
                      const float* __restrict__ fc_b,   // [1]
                      float* __restrict__ out)          // [B]
{
    __shared__ __align__(16) uint32_t hbuf[2][128];    // bf16x2, permuted
    __shared__ __align__(16) float    xs[XCH * NB];    // x chunk [t][n]

    const int tid = threadIdx.x;
    const int w   = tid >> 5;
    const int l   = tid & 31;
    const int gid = l >> 2;            // 0..7
    const int lq  = l & 3;             // 0..3
    const int b0  = blockIdx.x * NB;
    const int j   = 8 * w + gid;       // hidden unit owned in epilogue

    // A fragments (persistent, bf16): tile-mt rows 0-7 = gate 2mt (hidden 8w+r),
    // rows 8-15 = gate 2mt+1. Sigmoid gates (0,1,3) pre-scaled x0.5.
    uint32_t af[2][2][4];
    #pragma unroll
    for (int mt = 0; mt < 2; mt++) {
        const int g0 = 2 * mt, g1 = 2 * mt + 1;
        const float s0 = (g0 == 2) ? 1.0f : 0.5f;
        const float s1 = (g1 == 2) ? 1.0f : 0.5f;
        const float* r0 = W_hh + (g0 * HH + j) * HH;
        const float* r1 = W_hh + (g1 * HH + j) * HH;
        #pragma unroll
        for (int kt = 0; kt < 2; kt++) {
            const int k0 = kt * 16 + 2 * lq;
            af[mt][kt][0] = pack_bf16(r0[k0] * s0,     r0[k0 + 1] * s0);
            af[mt][kt][1] = pack_bf16(r1[k0] * s1,     r1[k0 + 1] * s1);
            af[mt][kt][2] = pack_bf16(r0[k0 + 8] * s0, r0[k0 + 9] * s0);
            af[mt][kt][3] = pack_bf16(r1[k0 + 8] * s1, r1[k0 + 9] * s1);
        }
    }

    float wih[4], bias[4];
    #pragma unroll
    for (int g = 0; g < 4; g++) {
        const float sc = (g == 2) ? 1.0f : 0.5f;
        wih[g]  = W_ih[g * HH + j] * sc;
        bias[g] = (b_ih[g * HH + j] + b_hh[g * HH + j]) * sc;
    }

    if (tid < 128) hbuf[0][tid] = 0u;

    // Hoisted addresses
    const uint32_t* bfp[2] = { &hbuf[0][lq * 16 + gid * 2],
                               &hbuf[1][lq * 16 + gid * 2] };
    // store: k=j -> kp=j>>1: word = (j>>4)*64 + ((j>>1)&3)*16 + n*2 + ((j>>3)&1)
    const int stw = (j >> 4) * 64 + ((j >> 1) & 3) * 16 + (2 * lq) * 2 + ((j >> 3) & 1);
    const int sth = (j & 1);
    uint16_t* stp[2] = {
        reinterpret_cast<uint16_t*>(&hbuf[0][stw]) + sth,
        reinterpret_cast<uint16_t*>(&hbuf[1][stw]) + sth };
    // cell dc=1 (n+1): word += 2 -> uint16 offset += 4

    float c[2] = {0.0f, 0.0f};

    #pragma unroll 1
    for (int tb = 0; tb < TT; tb += 2) {
        if ((tb & (XCH - 1)) == 0) {
            const int n = tid >> 4, part = tid & 15;
            const float4 v = *reinterpret_cast<const float4*>(
                x + (size_t)(b0 + n) * TT + tb + part * 4);
            xs[(part * 4 + 0) * NB + n] = v.x;
            xs[(part * 4 + 1) * NB + n] = v.y;
            xs[(part * 4 + 2) * NB + n] = v.z;
            xs[(part * 4 + 3) * NB + n] = v.w;
            __syncthreads();
        }

        #pragma unroll
        for (int ph = 0; ph < 2; ph++) {
            const int t = tb + ph;
            const int p = ph;                  // tb even -> parity == ph

            // acc init: fold x*W_ih + bias
            const float2 xv = *reinterpret_cast<const float2*>(
                &xs[(t & (XCH - 1)) * NB + 2 * lq]);
            float acc[2][4];
            #pragma unroll
            for (int mt = 0; mt < 2; mt++) {
                acc[mt][0] = fmaf(xv.x, wih[2 * mt],     bias[2 * mt]);
                acc[mt][1] = fmaf(xv.y, wih[2 * mt],     bias[2 * mt]);
                acc[mt][2] = fmaf(xv.x, wih[2 * mt + 1], bias[2 * mt + 1]);
                acc[mt][3] = fmaf(xv.y, wih[2 * mt + 1], bias[2 * mt + 1]);
            }

            // B fragments: one conflict-free LDS.64 per kt
            uint32_t bf[2][2];
            #pragma unroll
            for (int kt = 0; kt < 2; kt++) {
                const u64 v = *reinterpret_cast<const u64*>(bfp[p] + kt * 64);
                bf[kt][0] = (uint32_t)v;          // k = 2lq,2lq+1
                bf[kt][1] = (uint32_t)(v >> 32);  // k = 2lq+8,2lq+9
            }

            // 4 HMMAs: 2 independent chains of depth 2
            #pragma unroll
            for (int mt = 0; mt < 2; mt++) {
                mma_bf16(acc[mt], af[mt][0], bf[0]);
                mma_bf16(acc[mt], af[mt][1], bf[1]);
            }

            // epilogue: 2 cells (n = 2lq+dc, hidden j), registers only
            #pragma unroll
            for (int dc = 0; dc < 2; dc++) {
                const float gi = fmaf(0.5f, tanh_hw(acc[0][dc]),     0.5f);
                const float gf = fmaf(0.5f, tanh_hw(acc[0][2 + dc]), 0.5f);
                const float gg =             tanh_hw(acc[1][dc]);
                const float go = fmaf(0.5f, tanh_hw(acc[1][2 + dc]), 0.5f);
                c[dc] = fmaf(gf, c[dc], gi * gg);
                const float h = go * tanh_hw(c[dc]);
                __nv_bfloat16 hb = __float2bfloat16(h);
                stp[p ^ 1][dc * 4] = *reinterpret_cast<uint16_t*>(&hb);
            }

            __syncthreads();
        }
    }

    // out[n] = dot(h[n,:], fc_w) + fc_b   (final h in hbuf[0]: T even)
    if (tid < NB) {
        const int n = tid;
        const uint16_t* hb16 = reinterpret_cast<const uint16_t*>(hbuf[0]);
        float s = fc_b[0];
        #pragma unroll
        for (int k = 0; k < HH; k++) {
            const int word = (k >> 4) * 64 + ((k >> 1) & 3) * 16 + n * 2 + ((k >> 3) & 1);
            const uint16_t bits = hb16[word * 2 + (k & 1)];
            __nv_bfloat16 hv = *reinterpret_cast<const __nv_bfloat16*>(&bits);
            s = fmaf(__bfloat162float(hv), fc_w[k], s);
        }
        out[b0 + n] = s;
    }
}

extern "C" void kernel_launch(void* const* d_in, const int* in_sizes, int n_in,
                              void* d_out, int out_size) {
    const float* x    = (const float*)d_in[0];
    const float* W_ih = (const float*)d_in[1];
    const float* W_hh = (const float*)d_in[2];
    const float* b_ih = (const float*)d_in[3];
    const float* b_hh = (const float*)d_in[4];
    const float* fc_w = (const float*)d_in[5];
    const float* fc_b = (const float*)d_in[6];
    float* out = (float*)d_out;

    lstm_bf16_kernel<<<BB / NB, 128>>>(x, W_ih, W_hh, b_ih, b_hh, fc_w, fc_b, out);
}